// round 15
// baseline (speedup 1.0000x reference)
#include <cuda_runtime.h>
#include <cuda_fp16.h>
#include <cstdint>

// Problem-size maxima (fixed by the reference generator).
static constexpr int NMAX = 1000000;
static constexpr int GMAX = 1000;

// Node state AND aggregation buffer both packed as 8 fp16 (16B/row):
//  - h gather in edge pass = ONE divergent LDG.128
//  - agg scatter = ONE red.global.add.v4.f16x2
// uint4 guarantees 16B alignment.
__device__ uint4 g_h  [(size_t)NMAX];
__device__ uint4 g_agg[(size_t)NMAX];
__device__ float g_gsum[GMAX];
__device__ float g_gcnt[GMAX];

__device__ __forceinline__ unsigned f2h2(float a, float b) {
    __half2 p = __floats2half2_rn(a, b);
    return *reinterpret_cast<unsigned*>(&p);
}
__device__ __forceinline__ float2 h22f2(unsigned u) {
    return __half22float2(*reinterpret_cast<__half2*>(&u));
}
// h layout: {p01, p23, p45, 0}
__device__ __forceinline__ uint4 pack6(float v0, float v1, float v2,
                                       float v3, float v4, float v5) {
    return make_uint4(f2h2(v0, v1), f2h2(v2, v3), f2h2(v4, v5), 0u);
}
__device__ __forceinline__ void unpack6(uint4 v, float* a) {
    float2 f0 = h22f2(v.x), f1 = h22f2(v.y), f2 = h22f2(v.z);
    a[0] = f0.x; a[1] = f0.y; a[2] = f1.x; a[3] = f1.y; a[4] = f2.x; a[5] = f2.y;
}

// ---------------------------------------------------------------------------
// Init: h <- fp16(x), agg <- 0, pool accumulators <- 0.
// ---------------------------------------------------------------------------
__global__ __launch_bounds__(256) void init_kernel(const float* __restrict__ x,
                                                   int N, int G) {
    int i = blockIdx.x * 256 + threadIdx.x;
    if (i < N) {
        const float2* xp = reinterpret_cast<const float2*>(x + (size_t)i * 6);
        float2 a = __ldcs(xp + 0);
        float2 b = __ldcs(xp + 1);
        float2 c = __ldcs(xp + 2);
        g_h[i]   = pack6(a.x, a.y, b.x, b.y, c.x, c.y);
        g_agg[i] = make_uint4(0u, 0u, 0u, 0u);
    }
    if (i < G) { g_gsum[i] = 0.f; g_gcnt[i] = 0.f; }
}

// ---------------------------------------------------------------------------
// Edge pass: m = relu(h[src] + e); agg[dst] += fp16(m).
// One divergent LDG.128 gather + one 128-bit f16x2 vector reduction per edge.
// Message math in fp32 (single rounding at the reduction).
// ---------------------------------------------------------------------------
__global__ __launch_bounds__(256) void edge_kernel(const int* __restrict__ ei,
                                                   const float* __restrict__ ea,
                                                   int E) {
    int e = blockIdx.x * 256 + threadIdx.x;
    if (e >= E) return;
    int s = __ldcs(ei + e);
    int d = __ldcs(ei + (size_t)E + e);

    uint4 hv = __ldg(&g_h[s]);
    float h[6];
    unpack6(hv, h);

    const float2* ep = reinterpret_cast<const float2*>(ea + (size_t)e * 6);
    float2 e0 = __ldcs(ep + 0);
    float2 e1 = __ldcs(ep + 1);
    float2 e2 = __ldcs(ep + 2);

    float m0 = fmaxf(h[0] + e0.x, 0.f);
    float m1 = fmaxf(h[1] + e0.y, 0.f);
    float m2 = fmaxf(h[2] + e1.x, 0.f);
    float m3 = fmaxf(h[3] + e1.y, 0.f);
    float m4 = fmaxf(h[4] + e2.x, 0.f);
    float m5 = fmaxf(h[5] + e2.y, 0.f);

    uint4 m = pack6(m0, m1, m2, m3, m4, m5);
    unsigned long long ap =
        (unsigned long long)__cvta_generic_to_global(&g_agg[d]);
    asm volatile("red.global.add.noftz.v4.f16x2 [%0], {%1,%2,%3,%4};"
                 :: "l"(ap), "r"(m.x), "r"(m.y), "r"(m.z), "r"(0u) : "memory");
}

// ---------------------------------------------------------------------------
// Node update: h <- fp16(relu((h + agg) @ W + b)); agg <- 0.
// ---------------------------------------------------------------------------
__global__ __launch_bounds__(256) void node_kernel(const float* __restrict__ W,
                                                   const float* __restrict__ b,
                                                   int N) {
    __shared__ float sW[36];
    __shared__ float sb[6];
    if (threadIdx.x < 36) sW[threadIdx.x] = W[threadIdx.x];
    if (threadIdx.x < 6)  sb[threadIdx.x] = b[threadIdx.x];
    __syncthreads();

    int i = blockIdx.x * 256 + threadIdx.x;
    if (i >= N) return;

    float h[6], a[6];
    unpack6(g_h[i], h);
    unpack6(g_agg[i], a);

    float t[6] = {h[0] + a[0], h[1] + a[1], h[2] + a[2],
                  h[3] + a[3], h[4] + a[4], h[5] + a[5]};
    float y[6];
#pragma unroll
    for (int j = 0; j < 6; j++) {
        float acc = sb[j];
#pragma unroll
        for (int k = 0; k < 6; k++) acc = fmaf(t[k], sW[k * 6 + j], acc);
        y[j] = fmaxf(acc, 0.f);
    }

    g_h[i]   = pack6(y[0], y[1], y[2], y[3], y[4], y[5]);
    g_agg[i] = make_uint4(0u, 0u, 0u, 0u);
}

// ---------------------------------------------------------------------------
// Layer-3 node update fused with pooling head:
//   y = (h + agg) @ W3 + b3 (no relu);  s = y . Wl
//   pooled@Wl = (sum_i s_i)/cnt  -> accumulate (s, 1) per graph.
// batch (int32, sorted) -> warp-segmented reduction, ~1 atomic per run.
// ---------------------------------------------------------------------------
__global__ __launch_bounds__(256) void node3_kernel(const float* __restrict__ W,
                                                    const float* __restrict__ b,
                                                    const float* __restrict__ Wl,
                                                    const int* __restrict__ batch,
                                                    int N) {
    __shared__ float sW[36];
    __shared__ float sb[6];
    __shared__ float sWl[6];
    if (threadIdx.x < 36) sW[threadIdx.x] = W[threadIdx.x];
    if (threadIdx.x < 6) { sb[threadIdx.x] = b[threadIdx.x]; sWl[threadIdx.x] = Wl[threadIdx.x]; }
    __syncthreads();

    int i = blockIdx.x * 256 + threadIdx.x;
    float s = 0.f, c = 0.f;
    int g = -1;
    if (i < N) {
        float h[6], a[6];
        unpack6(g_h[i], h);
        unpack6(g_agg[i], a);
        float t[6] = {h[0] + a[0], h[1] + a[1], h[2] + a[2],
                      h[3] + a[3], h[4] + a[4], h[5] + a[5]};
#pragma unroll
        for (int j = 0; j < 6; j++) {
            float acc = sb[j];
#pragma unroll
            for (int k = 0; k < 6; k++) acc = fmaf(t[k], sW[k * 6 + j], acc);
            s = fmaf(acc, sWl[j], s);
        }
        c = 1.f;
        g = __ldg(batch + i);
    }

    // Segmented suffix reduction over sorted keys within the warp.
    int lane = threadIdx.x & 31;
#pragma unroll
    for (int off = 1; off < 32; off <<= 1) {
        float ov = __shfl_down_sync(0xFFFFFFFFu, s, off);
        float oc = __shfl_down_sync(0xFFFFFFFFu, c, off);
        int   og = __shfl_down_sync(0xFFFFFFFFu, g, off);
        if (lane + off < 32 && og == g) { s += ov; c += oc; }
    }
    int gprev = __shfl_up_sync(0xFFFFFFFFu, g, 1);
    bool head = (lane == 0) || (gprev != g);
    if (head && g >= 0) {
        atomicAdd(&g_gsum[g], s);
        atomicAdd(&g_gcnt[g], c);
    }
}

// ---------------------------------------------------------------------------
// Finalize: out[g] = gsum[g] / max(cnt, 1) + bl
// ---------------------------------------------------------------------------
__global__ __launch_bounds__(256) void final_kernel(const float* __restrict__ bl,
                                                    float* __restrict__ out, int G) {
    int g = blockIdx.x * 256 + threadIdx.x;
    if (g < G) out[g] = g_gsum[g] / fmaxf(g_gcnt[g], 1.f) + bl[0];
}

// ---------------------------------------------------------------------------
extern "C" void kernel_launch(void* const* d_in, const int* in_sizes, int n_in,
                              void* d_out, int out_size) {
    const float* x     = (const float*)d_in[0];
    const int*   ei    = (const int*)d_in[1];     // int32 (JAX x64 disabled)
    const float* ea    = (const float*)d_in[2];
    const int*   batch = (const int*)d_in[3];     // int32
    const float* W1 = (const float*)d_in[4];
    const float* b1 = (const float*)d_in[5];
    const float* W2 = (const float*)d_in[6];
    const float* b2 = (const float*)d_in[7];
    const float* W3 = (const float*)d_in[8];
    const float* b3 = (const float*)d_in[9];
    const float* Wl = (const float*)d_in[10];
    const float* bl = (const float*)d_in[11];
    float* out = (float*)d_out;

    int N = in_sizes[0] / 6;   // x is [N, 6]
    int E = in_sizes[2] / 6;   // edge_attr is [E, 6]
    int G = out_size;          // out is [G, 1]

    int nb = (N + 255) / 256;
    int eb = (E + 255) / 256;
    int gb = (G + 255) / 256;

    init_kernel<<<nb, 256>>>(x, N, G);

    edge_kernel<<<eb, 256>>>(ei, ea, E);
    node_kernel<<<nb, 256>>>(W1, b1, N);

    edge_kernel<<<eb, 256>>>(ei, ea, E);
    node_kernel<<<nb, 256>>>(W2, b2, N);

    edge_kernel<<<eb, 256>>>(ei, ea, E);
    node3_kernel<<<nb, 256>>>(W3, b3, Wl, batch, N);

    final_kernel<<<gb, 256>>>(bl, out, G);
}

// round 17
// speedup vs baseline: 1.0054x; 1.0054x over previous
#include <cuda_runtime.h>
#include <cuda_fp16.h>
#include <cstdint>

// Problem-size maxima (fixed by the reference generator).
static constexpr int NMAX = 1000000;
static constexpr int GMAX = 1000;

// Node state AND aggregation buffer both packed as 8 fp16 (16B/row):
//  - h gather in edge pass = ONE divergent LDG.128
//  - agg scatter = ONE red.global.add.v4.f16x2
// uint4 guarantees 16B alignment.
__device__ uint4 g_h  [(size_t)NMAX];
__device__ uint4 g_agg[(size_t)NMAX];
__device__ float g_gsum[GMAX];
__device__ float g_gcnt[GMAX];

__device__ __forceinline__ unsigned f2h2(float a, float b) {
    __half2 p = __floats2half2_rn(a, b);
    return *reinterpret_cast<unsigned*>(&p);
}
__device__ __forceinline__ float2 h22f2(unsigned u) {
    return __half22float2(*reinterpret_cast<__half2*>(&u));
}
// h layout: {p01, p23, p45, 0}
__device__ __forceinline__ uint4 pack6(float v0, float v1, float v2,
                                       float v3, float v4, float v5) {
    return make_uint4(f2h2(v0, v1), f2h2(v2, v3), f2h2(v4, v5), 0u);
}
__device__ __forceinline__ void unpack6(uint4 v, float* a) {
    float2 f0 = h22f2(v.x), f1 = h22f2(v.y), f2 = h22f2(v.z);
    a[0] = f0.x; a[1] = f0.y; a[2] = f1.x; a[3] = f1.y; a[4] = f2.x; a[5] = f2.y;
}

// ---------------------------------------------------------------------------
// Init: h <- fp16(x), agg <- 0, pool accumulators <- 0.
// ---------------------------------------------------------------------------
__global__ __launch_bounds__(256) void init_kernel(const float* __restrict__ x,
                                                   int N, int G) {
    int i = blockIdx.x * 256 + threadIdx.x;
    if (i < N) {
        const float2* xp = reinterpret_cast<const float2*>(x + (size_t)i * 6);
        float2 a = __ldcs(xp + 0);
        float2 b = __ldcs(xp + 1);
        float2 c = __ldcs(xp + 2);
        g_h[i]   = pack6(a.x, a.y, b.x, b.y, c.x, c.y);
        g_agg[i] = make_uint4(0u, 0u, 0u, 0u);
    }
    if (i < G) { g_gsum[i] = 0.f; g_gcnt[i] = 0.f; }
}

// ---------------------------------------------------------------------------
// Edge pass: m = relu(h[src] + e); agg[dst] += fp16(m).
// One divergent LDG.128 gather + one 128-bit f16x2 vector reduction per edge.
// Message math in fp32 (single rounding at the reduction).
// ---------------------------------------------------------------------------
__global__ __launch_bounds__(256) void edge_kernel(const int* __restrict__ ei,
                                                   const float* __restrict__ ea,
                                                   int E) {
    int e = blockIdx.x * 256 + threadIdx.x;
    if (e >= E) return;
    int s = __ldcs(ei + e);
    int d = __ldcs(ei + (size_t)E + e);

    uint4 hv = __ldg(&g_h[s]);
    float h[6];
    unpack6(hv, h);

    const float2* ep = reinterpret_cast<const float2*>(ea + (size_t)e * 6);
    float2 e0 = __ldcs(ep + 0);
    float2 e1 = __ldcs(ep + 1);
    float2 e2 = __ldcs(ep + 2);

    float m0 = fmaxf(h[0] + e0.x, 0.f);
    float m1 = fmaxf(h[1] + e0.y, 0.f);
    float m2 = fmaxf(h[2] + e1.x, 0.f);
    float m3 = fmaxf(h[3] + e1.y, 0.f);
    float m4 = fmaxf(h[4] + e2.x, 0.f);
    float m5 = fmaxf(h[5] + e2.y, 0.f);

    uint4 m = pack6(m0, m1, m2, m3, m4, m5);
    unsigned long long ap =
        (unsigned long long)__cvta_generic_to_global(&g_agg[d]);
    asm volatile("red.global.add.noftz.v4.f16x2 [%0], {%1,%2,%3,%4};"
                 :: "l"(ap), "r"(m.x), "r"(m.y), "r"(m.z), "r"(0u) : "memory");
}

// ---------------------------------------------------------------------------
// Node update: h <- fp16(relu((h + agg) @ W + b)); agg <- 0.
// ---------------------------------------------------------------------------
__global__ __launch_bounds__(256) void node_kernel(const float* __restrict__ W,
                                                   const float* __restrict__ b,
                                                   int N) {
    __shared__ float sW[36];
    __shared__ float sb[6];
    if (threadIdx.x < 36) sW[threadIdx.x] = W[threadIdx.x];
    if (threadIdx.x < 6)  sb[threadIdx.x] = b[threadIdx.x];
    __syncthreads();

    int i = blockIdx.x * 256 + threadIdx.x;
    if (i >= N) return;

    float h[6], a[6];
    unpack6(g_h[i], h);
    unpack6(g_agg[i], a);

    float t[6] = {h[0] + a[0], h[1] + a[1], h[2] + a[2],
                  h[3] + a[3], h[4] + a[4], h[5] + a[5]};
    float y[6];
#pragma unroll
    for (int j = 0; j < 6; j++) {
        float acc = sb[j];
#pragma unroll
        for (int k = 0; k < 6; k++) acc = fmaf(t[k], sW[k * 6 + j], acc);
        y[j] = fmaxf(acc, 0.f);
    }

    g_h[i]   = pack6(y[0], y[1], y[2], y[3], y[4], y[5]);
    g_agg[i] = make_uint4(0u, 0u, 0u, 0u);
}

// ---------------------------------------------------------------------------
// Layer-3 node update fused with pooling head:
//   y = (h + agg) @ W3 + b3 (no relu);  s = y . Wl
//   pooled@Wl = (sum_i s_i)/cnt  -> accumulate (s, 1) per graph.
// batch (int32, sorted) -> warp-segmented reduction, ~1 atomic per run.
// ---------------------------------------------------------------------------
__global__ __launch_bounds__(256) void node3_kernel(const float* __restrict__ W,
                                                    const float* __restrict__ b,
                                                    const float* __restrict__ Wl,
                                                    const int* __restrict__ batch,
                                                    int N) {
    __shared__ float sW[36];
    __shared__ float sb[6];
    __shared__ float sWl[6];
    if (threadIdx.x < 36) sW[threadIdx.x] = W[threadIdx.x];
    if (threadIdx.x < 6) { sb[threadIdx.x] = b[threadIdx.x]; sWl[threadIdx.x] = Wl[threadIdx.x]; }
    __syncthreads();

    int i = blockIdx.x * 256 + threadIdx.x;
    float s = 0.f, c = 0.f;
    int g = -1;
    if (i < N) {
        float h[6], a[6];
        unpack6(g_h[i], h);
        unpack6(g_agg[i], a);
        float t[6] = {h[0] + a[0], h[1] + a[1], h[2] + a[2],
                      h[3] + a[3], h[4] + a[4], h[5] + a[5]};
#pragma unroll
        for (int j = 0; j < 6; j++) {
            float acc = sb[j];
#pragma unroll
            for (int k = 0; k < 6; k++) acc = fmaf(t[k], sW[k * 6 + j], acc);
            s = fmaf(acc, sWl[j], s);
        }
        c = 1.f;
        g = __ldg(batch + i);
    }

    // Segmented suffix reduction over sorted keys within the warp.
    int lane = threadIdx.x & 31;
#pragma unroll
    for (int off = 1; off < 32; off <<= 1) {
        float ov = __shfl_down_sync(0xFFFFFFFFu, s, off);
        float oc = __shfl_down_sync(0xFFFFFFFFu, c, off);
        int   og = __shfl_down_sync(0xFFFFFFFFu, g, off);
        if (lane + off < 32 && og == g) { s += ov; c += oc; }
    }
    int gprev = __shfl_up_sync(0xFFFFFFFFu, g, 1);
    bool head = (lane == 0) || (gprev != g);
    if (head && g >= 0) {
        atomicAdd(&g_gsum[g], s);
        atomicAdd(&g_gcnt[g], c);
    }
}

// ---------------------------------------------------------------------------
// Finalize: out[g] = gsum[g] / max(cnt, 1) + bl
// ---------------------------------------------------------------------------
__global__ __launch_bounds__(256) void final_kernel(const float* __restrict__ bl,
                                                    float* __restrict__ out, int G) {
    int g = blockIdx.x * 256 + threadIdx.x;
    if (g < G) out[g] = g_gsum[g] / fmaxf(g_gcnt[g], 1.f) + bl[0];
}

// ---------------------------------------------------------------------------
extern "C" void kernel_launch(void* const* d_in, const int* in_sizes, int n_in,
                              void* d_out, int out_size) {
    const float* x     = (const float*)d_in[0];
    const int*   ei    = (const int*)d_in[1];     // int32 (JAX x64 disabled)
    const float* ea    = (const float*)d_in[2];
    const int*   batch = (const int*)d_in[3];     // int32
    const float* W1 = (const float*)d_in[4];
    const float* b1 = (const float*)d_in[5];
    const float* W2 = (const float*)d_in[6];
    const float* b2 = (const float*)d_in[7];
    const float* W3 = (const float*)d_in[8];
    const float* b3 = (const float*)d_in[9];
    const float* Wl = (const float*)d_in[10];
    const float* bl = (const float*)d_in[11];
    float* out = (float*)d_out;

    int N = in_sizes[0] / 6;   // x is [N, 6]
    int E = in_sizes[2] / 6;   // edge_attr is [E, 6]
    int G = out_size;          // out is [G, 1]

    int nb = (N + 255) / 256;
    int eb = (E + 255) / 256;
    int gb = (G + 255) / 256;

    init_kernel<<<nb, 256>>>(x, N, G);

    edge_kernel<<<eb, 256>>>(ei, ea, E);
    node_kernel<<<nb, 256>>>(W1, b1, N);

    edge_kernel<<<eb, 256>>>(ei, ea, E);
    node_kernel<<<nb, 256>>>(W2, b2, N);

    edge_kernel<<<eb, 256>>>(ei, ea, E);
    node3_kernel<<<nb, 256>>>(W3, b3, Wl, batch, N);

    final_kernel<<<gb, 256>>>(bl, out, G);
}